// round 1
// baseline (speedup 1.0000x reference)
#include <cuda_runtime.h>
#include <math.h>

#define T_TOK 4096      // B*S tokens
#define DIM   1024
#define NE    8
#define FF    4096
#define NPAIR (2*T_TOK)        // 8192 (token, expert) pairs, always
#define CAPP  9216             // 8192 + 8*128 padding (segments 128-aligned)

// ---------------- scratch (device globals; no allocation allowed) ----------
__device__ float g_H[(size_t)CAPP * FF];   // SiLU(x@W1+b1) per pair row
__device__ int   g_pair_tok[CAPP];         // token index per pair row (-1 = pad)
__device__ float g_pair_sc[CAPP];          // routing score per pair row
__device__ int   g_tok_e[NPAIR];           // per-token top-2 expert ids
__device__ float g_tok_p[NPAIR];           // per-token top-2 probs
__device__ int   g_counts[NE];
__device__ int   g_cursor[NE];
__device__ int   g_seg[NE + 1];            // 128-aligned segment starts

// ---------------- small utility kernels ------------------------------------
__global__ void k_zero_out(float4* out) {
    int i = blockIdx.x * blockDim.x + threadIdx.x;   // T_TOK*DIM/4 elements
    out[i] = make_float4(0.f, 0.f, 0.f, 0.f);
}

__global__ void k_reset() {
    int i = threadIdx.x;
    if (i < NE) { g_counts[i] = 0; g_cursor[i] = 0; }
}

// ---------------- router: logits -> top2 -> softmax(top2) ------------------
__global__ void __launch_bounds__(128) k_router(
    const float* __restrict__ x, const float* __restrict__ noise,
    const float* __restrict__ gw, const float* __restrict__ gb,
    const float* __restrict__ nw, const float* __restrict__ nb)
{
    int t = blockIdx.x;
    int tid = threadIdx.x;
    __shared__ float sx[DIM];
    __shared__ float red[128];
    __shared__ float lg[NE];

    for (int i = tid; i < DIM; i += 128) sx[i] = x[(size_t)t * DIM + i];
    __syncthreads();

    int e = tid & 7;
    float s = 0.f;
    for (int d = (tid >> 3); d < DIM; d += 16)
        s += sx[d] * (gw[d * NE + e] + nw[d * NE + e]);
    red[tid] = s;
    __syncthreads();
    for (int off = 64; off >= 8; off >>= 1) {
        if (tid < off) red[tid] += red[tid + off];
        __syncthreads();
    }
    if (tid < NE)
        lg[tid] = red[tid] + gb[tid] + nb[tid] + noise[t * NE + tid];
    __syncthreads();

    if (tid == 0) {
        float v0 = -1e30f; int i0 = 0;
        #pragma unroll
        for (int k = 0; k < NE; k++) { float v = lg[k]; if (v > v0) { v0 = v; i0 = k; } }
        float v1 = -1e30f; int i1 = 0;
        #pragma unroll
        for (int k = 0; k < NE; k++) { if (k == i0) continue; float v = lg[k]; if (v > v1) { v1 = v; i1 = k; } }
        float e1 = expf(v1 - v0);          // v0 >= v1, numerically stable
        float z = 1.f + e1;
        float p0 = 1.f / z, p1 = e1 / z;
        g_tok_e[2 * t] = i0;  g_tok_e[2 * t + 1] = i1;
        g_tok_p[2 * t] = p0;  g_tok_p[2 * t + 1] = p1;
        atomicAdd(&g_counts[i0], 1);
        atomicAdd(&g_counts[i1], 1);
    }
}

__global__ void k_offsets() {
    if (threadIdx.x == 0) {
        int acc = 0;
        g_seg[0] = 0;
        for (int e = 0; e < NE; e++) {
            acc += ((g_counts[e] + 127) / 128) * 128;
            g_seg[e + 1] = acc;
        }
    }
}

__global__ void k_init_pairs() {
    int i = blockIdx.x * blockDim.x + threadIdx.x;
    if (i < CAPP) { g_pair_tok[i] = -1; g_pair_sc[i] = 0.f; }
}

__global__ void k_scatter() {
    int i = blockIdx.x * blockDim.x + threadIdx.x;   // over NPAIR
    if (i >= NPAIR) return;
    int t = i >> 1;
    int e = g_tok_e[i];
    float p = g_tok_p[i];
    int pos = g_seg[e] + atomicAdd(&g_cursor[e], 1);
    g_pair_tok[pos] = t;
    g_pair_sc[pos]  = p;
}

// ---------------- expert lookup for a 128-row tile --------------------------
__device__ __forceinline__ int tile_expert(int row0) {
    int e = -1;
    #pragma unroll
    for (int i = 0; i < NE; i++)
        if (row0 >= g_seg[i] && row0 < g_seg[i + 1]) e = i;
    return e;
}

// ---------------- GEMM1: H = SiLU(X_gather @ W1[e] + b1[e]) -----------------
// tiles 128x128, K-tile 8, 256 threads, 8x8 per-thread micro tile
__global__ void __launch_bounds__(256, 2) k_gemm1(
    const float* __restrict__ x, const float* __restrict__ w1,
    const float* __restrict__ b1)
{
    int n0 = blockIdx.x * 128;
    int row0 = blockIdx.y * 128;
    int e = tile_expert(row0);
    if (e < 0) return;
    const float* __restrict__ w = w1 + (size_t)e * DIM * FF;

    __shared__ float As[8][132];
    __shared__ float Bs[8][128];
    __shared__ int stok[128];

    int tid = threadIdx.x;
    if (tid < 128) stok[tid] = g_pair_tok[row0 + tid];
    __syncthreads();

    float acc[8][8];
    #pragma unroll
    for (int i = 0; i < 8; i++)
        #pragma unroll
        for (int j = 0; j < 8; j++) acc[i][j] = 0.f;

    int tm = (tid >> 4) << 3;
    int tn = (tid & 15) << 3;

    for (int k0 = 0; k0 < DIM; k0 += 8) {
        #pragma unroll
        for (int i = 0; i < 4; i++) {
            int idx = tid + i * 256;
            int m = idx >> 3, kk = idx & 7;
            int t = stok[m];
            As[kk][m] = (t >= 0) ? x[(size_t)t * DIM + k0 + kk] : 0.f;
        }
        #pragma unroll
        for (int i = 0; i < 4; i++) {
            int idx = tid + i * 256;
            int kk = idx >> 7, n = idx & 127;
            Bs[kk][n] = w[(size_t)(k0 + kk) * FF + n0 + n];
        }
        __syncthreads();
        #pragma unroll
        for (int kk = 0; kk < 8; kk++) {
            float4 a0 = *(const float4*)&As[kk][tm];
            float4 a1 = *(const float4*)&As[kk][tm + 4];
            float4 b0 = *(const float4*)&Bs[kk][tn];
            float4 b1v = *(const float4*)&Bs[kk][tn + 4];
            float a[8] = {a0.x, a0.y, a0.z, a0.w, a1.x, a1.y, a1.z, a1.w};
            float b[8] = {b0.x, b0.y, b0.z, b0.w, b1v.x, b1v.y, b1v.z, b1v.w};
            #pragma unroll
            for (int i = 0; i < 8; i++)
                #pragma unroll
                for (int j = 0; j < 8; j++)
                    acc[i][j] += a[i] * b[j];
        }
        __syncthreads();
    }

    // epilogue: bias + SiLU -> g_H
    #pragma unroll
    for (int i = 0; i < 8; i++) {
        int row = row0 + tm + i;
        #pragma unroll
        for (int j4 = 0; j4 < 2; j4++) {
            float4 v;
            float* vp = (float*)&v;
            #pragma unroll
            for (int q = 0; q < 4; q++) {
                int n = n0 + tn + j4 * 4 + q;
                float a = acc[i][j4 * 4 + q] + b1[e * FF + n];
                vp[q] = a / (1.f + expf(-a));
            }
            *(float4*)&g_H[(size_t)row * FF + n0 + tn + j4 * 4] = v;
        }
    }
}

// ---------------- GEMM2: out[t] += score * (H @ W2[e] + b2[e]) --------------
__global__ void __launch_bounds__(256, 2) k_gemm2(
    const float* __restrict__ w2, const float* __restrict__ b2,
    float* __restrict__ out)
{
    int n0 = blockIdx.x * 128;
    int row0 = blockIdx.y * 128;
    int e = tile_expert(row0);
    if (e < 0) return;
    const float* __restrict__ w = w2 + (size_t)e * FF * DIM;

    __shared__ float As[8][132];
    __shared__ float Bs[8][128];
    __shared__ int   stok[128];
    __shared__ float ssc[128];

    int tid = threadIdx.x;
    if (tid < 128) { stok[tid] = g_pair_tok[row0 + tid]; ssc[tid] = g_pair_sc[row0 + tid]; }
    __syncthreads();

    float acc[8][8];
    #pragma unroll
    for (int i = 0; i < 8; i++)
        #pragma unroll
        for (int j = 0; j < 8; j++) acc[i][j] = 0.f;

    int tm = (tid >> 4) << 3;
    int tn = (tid & 15) << 3;

    for (int k0 = 0; k0 < FF; k0 += 8) {
        #pragma unroll
        for (int i = 0; i < 4; i++) {
            int idx = tid + i * 256;
            int m = idx >> 3, kk = idx & 7;
            As[kk][m] = g_H[(size_t)(row0 + m) * FF + k0 + kk];
        }
        #pragma unroll
        for (int i = 0; i < 4; i++) {
            int idx = tid + i * 256;
            int kk = idx >> 7, n = idx & 127;
            Bs[kk][n] = w[(size_t)(k0 + kk) * DIM + n0 + n];
        }
        __syncthreads();
        #pragma unroll
        for (int kk = 0; kk < 8; kk++) {
            float4 a0 = *(const float4*)&As[kk][tm];
            float4 a1 = *(const float4*)&As[kk][tm + 4];
            float4 b0 = *(const float4*)&Bs[kk][tn];
            float4 b1v = *(const float4*)&Bs[kk][tn + 4];
            float a[8] = {a0.x, a0.y, a0.z, a0.w, a1.x, a1.y, a1.z, a1.w};
            float b[8] = {b0.x, b0.y, b0.z, b0.w, b1v.x, b1v.y, b1v.z, b1v.w};
            #pragma unroll
            for (int i = 0; i < 8; i++)
                #pragma unroll
                for (int j = 0; j < 8; j++)
                    acc[i][j] += a[i] * b[j];
        }
        __syncthreads();
    }

    #pragma unroll
    for (int i = 0; i < 8; i++) {
        int m = tm + i;
        int t = stok[m];
        if (t < 0) continue;
        float s = ssc[m];
        #pragma unroll
        for (int j = 0; j < 8; j++) {
            int n = n0 + tn + j;
            float y = acc[i][j] + b2[e * DIM + n];
            atomicAdd(&out[(size_t)t * DIM + n], s * y);
        }
    }
}

// ---------------- aux loss ---------------------------------------------------
__global__ void __launch_bounds__(256) k_aux(float* __restrict__ aux_out) {
    __shared__ float sred[256];
    __shared__ float simp[NE];
    int tid = threadIdx.x;
    float imp[NE];
    #pragma unroll
    for (int e = 0; e < NE; e++) imp[e] = 0.f;
    for (int t = tid; t < T_TOK; t += 256) {
        imp[g_tok_e[2 * t]]     += g_tok_p[2 * t];
        imp[g_tok_e[2 * t + 1]] += g_tok_p[2 * t + 1];
    }
    for (int e = 0; e < NE; e++) {
        sred[tid] = imp[e];
        __syncthreads();
        for (int off = 128; off > 0; off >>= 1) {
            if (tid < off) sred[tid] += sred[tid + off];
            __syncthreads();
        }
        if (tid == 0) simp[e] = sred[0] / (float)T_TOK;
        __syncthreads();
    }
    if (tid == 0) {
        float aux = 0.f;
        const float u = 1.f / (float)NE;
        const float logu = logf(u);
        #pragma unroll
        for (int e = 0; e < NE; e++)
            aux += u * (logu - logf(simp[e] + 1e-8f));
        aux_out[0] = aux;
    }
}

// ---------------- launch -----------------------------------------------------
extern "C" void kernel_launch(void* const* d_in, const int* in_sizes, int n_in,
                              void* d_out, int out_size) {
    const float* x       = (const float*)d_in[0];
    const float* noise   = (const float*)d_in[1];
    const float* gate_w  = (const float*)d_in[2];
    const float* gate_b  = (const float*)d_in[3];
    const float* noise_w = (const float*)d_in[4];
    const float* noise_b = (const float*)d_in[5];
    const float* w1      = (const float*)d_in[6];
    const float* b1      = (const float*)d_in[7];
    const float* w2      = (const float*)d_in[8];
    const float* b2      = (const float*)d_in[9];
    float* out = (float*)d_out;

    (void)in_sizes; (void)n_in;

    // 1. zero output accumulator
    k_zero_out<<<(T_TOK * DIM / 4 + 255) / 256, 256>>>((float4*)out);
    // 2. reset counters
    k_reset<<<1, 32>>>();
    // 3. router + top2 + softmax
    k_router<<<T_TOK, 128>>>(x, noise, gate_w, gate_b, noise_w, noise_b);
    // 4. padded segment offsets
    k_offsets<<<1, 32>>>();
    // 5. init pair arrays (pads = -1)
    k_init_pairs<<<(CAPP + 255) / 256, 256>>>();
    // 6. scatter pairs into expert-grouped, 128-padded rows
    k_scatter<<<(NPAIR + 255) / 256, 256>>>();
    // 7. expert GEMM1 + SiLU
    k_gemm1<<<dim3(FF / 128, CAPP / 128), 256>>>(x, w1, b1);
    // 8. expert GEMM2 + scaled scatter-add
    k_gemm2<<<dim3(DIM / 128, CAPP / 128), 256>>>(w2, b2, out);
    // 9. aux loss -> last output element
    k_aux<<<1, 256>>>(out + (out_size - 1));
}

// round 3
// speedup vs baseline: 3.0519x; 3.0519x over previous
#include <cuda_runtime.h>
#include <math.h>
#include <stdint.h>

#define T_TOK 4096      // B*S tokens
#define DIM   1024
#define NE    8
#define FF    4096
#define NPAIR (2*T_TOK)        // 8192 (token, expert) pairs
#define CAPP  9216             // 8192 + 8*128 padding (segments 128-aligned)

// ---------------- scratch (device globals; no allocation allowed) ----------
__device__ float g_H[(size_t)CAPP * FF];   // SiLU(x@W1+b1) per pair row
__device__ int   g_pair_tok[CAPP];         // token index per pair row (-1 = pad)
__device__ float g_pair_sc[CAPP];          // routing score per pair row
__device__ int   g_tok_e[NPAIR];
__device__ float g_tok_p[NPAIR];
__device__ int   g_counts[NE];
__device__ int   g_cursor[NE];
__device__ int   g_seg[NE + 1];            // 128-aligned segment starts

// ---------------- helpers ----------------------------------------------------
__device__ __forceinline__ uint32_t f2tf(float f) {     // fp32 -> tf32 (RN)
    uint32_t u;
    asm("cvt.rna.tf32.f32 %0, %1;" : "=r"(u) : "f"(f));
    return u;
}

__device__ __forceinline__ void mma_tf32(float& c0, float& c1, float& c2, float& c3,
                                         uint32_t a0, uint32_t a1, uint32_t a2, uint32_t a3,
                                         uint32_t b0, uint32_t b1) {
    asm volatile(
        "mma.sync.aligned.m16n8k8.row.col.f32.tf32.tf32.f32 "
        "{%0,%1,%2,%3}, {%4,%5,%6,%7}, {%8,%9}, {%0,%1,%2,%3};"
        : "+f"(c0), "+f"(c1), "+f"(c2), "+f"(c3)
        : "r"(a0), "r"(a1), "r"(a2), "r"(a3), "r"(b0), "r"(b1));
}

// ---------------- small utility kernels ------------------------------------
__global__ void k_zero_out(float4* out) {
    int i = blockIdx.x * blockDim.x + threadIdx.x;
    out[i] = make_float4(0.f, 0.f, 0.f, 0.f);
}
__global__ void k_reset() {
    int i = threadIdx.x;
    if (i < NE) { g_counts[i] = 0; g_cursor[i] = 0; }
}

// ---------------- router: logits -> top2 -> softmax(top2) ------------------
__global__ void __launch_bounds__(128) k_router(
    const float* __restrict__ x, const float* __restrict__ noise,
    const float* __restrict__ gw, const float* __restrict__ gb,
    const float* __restrict__ nw, const float* __restrict__ nb)
{
    int t = blockIdx.x;
    int tid = threadIdx.x;
    __shared__ float sx[DIM];
    __shared__ float red[128];
    __shared__ float lg[NE];

    for (int i = tid; i < DIM; i += 128) sx[i] = x[(size_t)t * DIM + i];
    __syncthreads();

    int e = tid & 7;
    float s = 0.f;
    for (int d = (tid >> 3); d < DIM; d += 16)
        s += sx[d] * (gw[d * NE + e] + nw[d * NE + e]);
    red[tid] = s;
    __syncthreads();
    for (int off = 64; off >= 8; off >>= 1) {
        if (tid < off) red[tid] += red[tid + off];
        __syncthreads();
    }
    if (tid < NE)
        lg[tid] = red[tid] + gb[tid] + nb[tid] + noise[t * NE + tid];
    __syncthreads();

    if (tid == 0) {
        float v0 = -1e30f; int i0 = 0;
        #pragma unroll
        for (int k = 0; k < NE; k++) { float v = lg[k]; if (v > v0) { v0 = v; i0 = k; } }
        float v1 = -1e30f; int i1 = 0;
        #pragma unroll
        for (int k = 0; k < NE; k++) { if (k == i0) continue; float v = lg[k]; if (v > v1) { v1 = v; i1 = k; } }
        float e1 = expf(v1 - v0);
        float z = 1.f + e1;
        g_tok_e[2 * t] = i0;  g_tok_e[2 * t + 1] = i1;
        g_tok_p[2 * t] = 1.f / z;  g_tok_p[2 * t + 1] = e1 / z;
        atomicAdd(&g_counts[i0], 1);
        atomicAdd(&g_counts[i1], 1);
    }
}

__global__ void k_offsets() {
    if (threadIdx.x == 0) {
        int acc = 0;
        g_seg[0] = 0;
        for (int e = 0; e < NE; e++) {
            acc += ((g_counts[e] + 127) / 128) * 128;
            g_seg[e + 1] = acc;
        }
    }
}

__global__ void k_init_pairs() {
    int i = blockIdx.x * blockDim.x + threadIdx.x;
    if (i < CAPP) { g_pair_tok[i] = -1; g_pair_sc[i] = 0.f; }
}

__global__ void k_scatter() {
    int i = blockIdx.x * blockDim.x + threadIdx.x;
    if (i >= NPAIR) return;
    int t = i >> 1;
    int e = g_tok_e[i];
    float p = g_tok_p[i];
    int pos = g_seg[e] + atomicAdd(&g_cursor[e], 1);
    g_pair_tok[pos] = t;
    g_pair_sc[pos]  = p;
}

__device__ __forceinline__ int tile_expert(int row0) {
    int e = -1;
    #pragma unroll
    for (int i = 0; i < NE; i++)
        if (row0 >= g_seg[i] && row0 < g_seg[i + 1]) e = i;
    return e;
}

// ---------------- SMEM strides (conflict-free fragment reads) ---------------
#define AST 36    // As[128][36]: bank = (4m+k)%32, distinct
#define BST 132   // Bs[32][132]: bank = (4k+n)%32, distinct

// =============================================================================
// tf32 mma.sync GEMM core: 128x128 CTA tile, 8 warps (64x32 each), K-tile 32
// =============================================================================

// GEMM1: H = SiLU(X_gather @ W1[e] + b1[e]);   W1 row-major [K=DIM][N=FF]
__global__ void __launch_bounds__(256, 2) k_mma_gemm1(
    const float* __restrict__ x, const float* __restrict__ w1,
    const float* __restrict__ b1)
{
    __shared__ uint32_t As[128 * AST];
    __shared__ uint32_t Bs[32 * BST];
    __shared__ int stok[128];

    const int tid = threadIdx.x;
    const int n0 = blockIdx.x * 128;
    const int row0 = blockIdx.y * 128;
    const int e = tile_expert(row0);
    if (e < 0) return;
    const float* __restrict__ w = w1 + (size_t)e * DIM * FF;

    if (tid < 128) stok[tid] = g_pair_tok[row0 + tid];
    __syncthreads();

    const int lane = tid & 31;
    const int wrp = tid >> 5;
    const int wm = (wrp & 1) * 64;
    const int wn = (wrp >> 1) * 32;
    const int qr = lane >> 2;   // 0..7
    const int qk = lane & 3;    // 0..3

    float acc[4][4][4];
    #pragma unroll
    for (int i = 0; i < 4; i++)
        #pragma unroll
        for (int j = 0; j < 4; j++)
            #pragma unroll
            for (int q = 0; q < 4; q++) acc[i][j][q] = 0.f;

    // per-thread A-load coords (4 float4s per k-tile)
    const int arow = tid >> 1;            // 0..127
    const int t_a = stok[arow];
    const float* __restrict__ xrow = (t_a >= 0) ? x + (size_t)t_a * DIM : x;

    for (int kt = 0; kt < DIM; kt += 32) {
        // ---- load A (gather + tf32) ----
        #pragma unroll
        for (int i = 0; i < 2; ++i) {
            int kq = (tid & 1) * 4 + i * 2;   // float4 index 0..7 (two per thread... )
            // each thread does 2 float4s covering rows tid>>1, cols {kq, kq+... }
            float4 v = (t_a >= 0) ? *(const float4*)(xrow + kt + kq * 4)
                                  : make_float4(0.f, 0.f, 0.f, 0.f);
            uint4 u = make_uint4(f2tf(v.x), f2tf(v.y), f2tf(v.z), f2tf(v.w));
            *(uint4*)&As[arow * AST + kq * 4] = u;
        }
        // remaining half of the row's 32 k-values
        #pragma unroll
        for (int i = 0; i < 2; ++i) {
            int kq = (tid & 1) * 4 + i * 2 + 1;
            float4 v = (t_a >= 0) ? *(const float4*)(xrow + kt + kq * 4)
                                  : make_float4(0.f, 0.f, 0.f, 0.f);
            uint4 u = make_uint4(f2tf(v.x), f2tf(v.y), f2tf(v.z), f2tf(v.w));
            *(uint4*)&As[arow * AST + kq * 4] = u;
        }
        // ---- load B (tf32) ----
        #pragma unroll
        for (int i = 0; i < 4; ++i) {
            int idx = tid + i * 256;          // 0..1023
            int kk = idx >> 5, nq = idx & 31;
            float4 v = *(const float4*)(w + (size_t)(kt + kk) * FF + n0 + nq * 4);
            uint4 u = make_uint4(f2tf(v.x), f2tf(v.y), f2tf(v.z), f2tf(v.w));
            *(uint4*)&Bs[kk * BST + nq * 4] = u;
        }
        __syncthreads();

        // ---- 4 x k=8 mma steps ----
        #pragma unroll
        for (int ks = 0; ks < 4; ++ks) {
            const int k0 = ks * 8;
            uint32_t af[4][4];
            #pragma unroll
            for (int i = 0; i < 4; ++i) {
                int m = wm + i * 16 + qr;
                af[i][0] = As[m * AST + k0 + qk];
                af[i][1] = As[(m + 8) * AST + k0 + qk];
                af[i][2] = As[m * AST + k0 + qk + 4];
                af[i][3] = As[(m + 8) * AST + k0 + qk + 4];
            }
            uint32_t bf[4][2];
            #pragma unroll
            for (int j = 0; j < 4; ++j) {
                int n = wn + j * 8 + qr;
                bf[j][0] = Bs[(k0 + qk) * BST + n];
                bf[j][1] = Bs[(k0 + qk + 4) * BST + n];
            }
            #pragma unroll
            for (int i = 0; i < 4; ++i)
                #pragma unroll
                for (int j = 0; j < 4; ++j)
                    mma_tf32(acc[i][j][0], acc[i][j][1], acc[i][j][2], acc[i][j][3],
                             af[i][0], af[i][1], af[i][2], af[i][3],
                             bf[j][0], bf[j][1]);
        }
        __syncthreads();
    }

    // ---- epilogue: bias + SiLU -> g_H ----
    const float* bp = b1 + (size_t)e * FF + n0;
    #pragma unroll
    for (int j = 0; j < 4; ++j) {
        int col = wn + j * 8 + (lane & 3) * 2;
        float bb0 = bp[col], bb1 = bp[col + 1];
        #pragma unroll
        for (int i = 0; i < 4; ++i) {
            int r0 = row0 + wm + i * 16 + qr;
            float a0 = acc[i][j][0] + bb0, a1 = acc[i][j][1] + bb1;
            float2 o0 = make_float2(a0 / (1.f + __expf(-a0)), a1 / (1.f + __expf(-a1)));
            *(float2*)&g_H[(size_t)r0 * FF + n0 + col] = o0;
            float a2 = acc[i][j][2] + bb0, a3 = acc[i][j][3] + bb1;
            float2 o1 = make_float2(a2 / (1.f + __expf(-a2)), a3 / (1.f + __expf(-a3)));
            *(float2*)&g_H[(size_t)(r0 + 8) * FF + n0 + col] = o1;
        }
    }
}

// GEMM2: out[t] += score * (H @ W2[e] + b2[e]);  W2 row-major [K=FF][N=DIM]
__global__ void __launch_bounds__(256, 2) k_mma_gemm2(
    const float* __restrict__ w2, const float* __restrict__ b2,
    float* __restrict__ out)
{
    __shared__ uint32_t As[128 * AST];
    __shared__ uint32_t Bs[32 * BST];
    __shared__ int   stok[128];
    __shared__ float ssc[128];

    const int tid = threadIdx.x;
    const int n0 = blockIdx.x * 128;
    const int row0 = blockIdx.y * 128;
    const int e = tile_expert(row0);
    if (e < 0) return;
    const float* __restrict__ w = w2 + (size_t)e * FF * DIM;

    if (tid < 128) { stok[tid] = g_pair_tok[row0 + tid]; ssc[tid] = g_pair_sc[row0 + tid]; }
    __syncthreads();

    const int lane = tid & 31;
    const int wrp = tid >> 5;
    const int wm = (wrp & 1) * 64;
    const int wn = (wrp >> 1) * 32;
    const int qr = lane >> 2;
    const int qk = lane & 3;

    float acc[4][4][4];
    #pragma unroll
    for (int i = 0; i < 4; i++)
        #pragma unroll
        for (int j = 0; j < 4; j++)
            #pragma unroll
            for (int q = 0; q < 4; q++) acc[i][j][q] = 0.f;

    const int arow = tid >> 1;
    const float* __restrict__ hrow = g_H + (size_t)(row0 + arow) * FF;

    for (int kt = 0; kt < FF; kt += 32) {
        #pragma unroll
        for (int i = 0; i < 4; ++i) {
            int kq = (tid & 1) * 4 + i;       // float4 index 0..7
            float4 v = *(const float4*)(hrow + kt + kq * 4);
            uint4 u = make_uint4(f2tf(v.x), f2tf(v.y), f2tf(v.z), f2tf(v.w));
            *(uint4*)&As[arow * AST + kq * 4] = u;
        }
        #pragma unroll
        for (int i = 0; i < 4; ++i) {
            int idx = tid + i * 256;
            int kk = idx >> 5, nq = idx & 31;
            float4 v = *(const float4*)(w + (size_t)(kt + kk) * DIM + n0 + nq * 4);
            uint4 u = make_uint4(f2tf(v.x), f2tf(v.y), f2tf(v.z), f2tf(v.w));
            *(uint4*)&Bs[kk * BST + nq * 4] = u;
        }
        __syncthreads();

        #pragma unroll
        for (int ks = 0; ks < 4; ++ks) {
            const int k0 = ks * 8;
            uint32_t af[4][4];
            #pragma unroll
            for (int i = 0; i < 4; ++i) {
                int m = wm + i * 16 + qr;
                af[i][0] = As[m * AST + k0 + qk];
                af[i][1] = As[(m + 8) * AST + k0 + qk];
                af[i][2] = As[m * AST + k0 + qk + 4];
                af[i][3] = As[(m + 8) * AST + k0 + qk + 4];
            }
            uint32_t bf[4][2];
            #pragma unroll
            for (int j = 0; j < 4; ++j) {
                int n = wn + j * 8 + qr;
                bf[j][0] = Bs[(k0 + qk) * BST + n];
                bf[j][1] = Bs[(k0 + qk + 4) * BST + n];
            }
            #pragma unroll
            for (int i = 0; i < 4; ++i)
                #pragma unroll
                for (int j = 0; j < 4; ++j)
                    mma_tf32(acc[i][j][0], acc[i][j][1], acc[i][j][2], acc[i][j][3],
                             af[i][0], af[i][1], af[i][2], af[i][3],
                             bf[j][0], bf[j][1]);
        }
        __syncthreads();
    }

    // ---- epilogue: bias + score * atomicAdd ----
    const float* bp = b2 + (size_t)e * DIM + n0;
    #pragma unroll
    for (int j = 0; j < 4; ++j) {
        int col = wn + j * 8 + (lane & 3) * 2;
        float bb0 = bp[col], bb1 = bp[col + 1];
        #pragma unroll
        for (int i = 0; i < 4; ++i) {
            int m = wm + i * 16 + qr;
            int t0 = stok[m], t1 = stok[m + 8];
            if (t0 >= 0) {
                float s = ssc[m];
                atomicAdd(&out[(size_t)t0 * DIM + n0 + col],     s * (acc[i][j][0] + bb0));
                atomicAdd(&out[(size_t)t0 * DIM + n0 + col + 1], s * (acc[i][j][1] + bb1));
            }
            if (t1 >= 0) {
                float s = ssc[m + 8];
                atomicAdd(&out[(size_t)t1 * DIM + n0 + col],     s * (acc[i][j][2] + bb0));
                atomicAdd(&out[(size_t)t1 * DIM + n0 + col + 1], s * (acc[i][j][3] + bb1));
            }
        }
    }
}

// ---------------- aux loss ---------------------------------------------------
__global__ void __launch_bounds__(256) k_aux(float* __restrict__ aux_out) {
    __shared__ float sred[256];
    __shared__ float simp[NE];
    int tid = threadIdx.x;
    float imp[NE];
    #pragma unroll
    for (int e = 0; e < NE; e++) imp[e] = 0.f;
    for (int t = tid; t < T_TOK; t += 256) {
        imp[g_tok_e[2 * t]]     += g_tok_p[2 * t];
        imp[g_tok_e[2 * t + 1]] += g_tok_p[2 * t + 1];
    }
    for (int e = 0; e < NE; e++) {
        sred[tid] = imp[e];
        __syncthreads();
        for (int off = 128; off > 0; off >>= 1) {
            if (tid < off) sred[tid] += sred[tid + off];
            __syncthreads();
        }
        if (tid == 0) simp[e] = sred[0] / (float)T_TOK;
        __syncthreads();
    }
    if (tid == 0) {
        float aux = 0.f;
        const float u = 1.f / (float)NE;
        const float logu = logf(u);
        #pragma unroll
        for (int e = 0; e < NE; e++)
            aux += u * (logu - logf(simp[e] + 1e-8f));
        aux_out[0] = aux;
    }
}

// ---------------- launch -----------------------------------------------------
extern "C" void kernel_launch(void* const* d_in, const int* in_sizes, int n_in,
                              void* d_out, int out_size) {
    const float* x       = (const float*)d_in[0];
    const float* noise   = (const float*)d_in[1];
    const float* gate_w  = (const float*)d_in[2];
    const float* gate_b  = (const float*)d_in[3];
    const float* noise_w = (const float*)d_in[4];
    const float* noise_b = (const float*)d_in[5];
    const float* w1      = (const float*)d_in[6];
    const float* b1      = (const float*)d_in[7];
    const float* w2      = (const float*)d_in[8];
    const float* b2      = (const float*)d_in[9];
    float* out = (float*)d_out;
    (void)in_sizes; (void)n_in;

    k_zero_out<<<(T_TOK * DIM / 4 + 255) / 256, 256>>>((float4*)out);
    k_reset<<<1, 32>>>();
    k_router<<<T_TOK, 128>>>(x, noise, gate_w, gate_b, noise_w, noise_b);
    k_offsets<<<1, 32>>>();
    k_init_pairs<<<(CAPP + 255) / 256, 256>>>();
    k_scatter<<<(NPAIR + 255) / 256, 256>>>();
    k_mma_gemm1<<<dim3(FF / 128, CAPP / 128), 256>>>(x, w1, b1);
    k_mma_gemm2<<<dim3(DIM / 128, CAPP / 128), 256>>>(w2, b2, out);
    k_aux<<<1, 256>>>(out + (out_size - 1));
}

// round 4
// speedup vs baseline: 4.0878x; 1.3394x over previous
#include <cuda_runtime.h>
#include <cuda_fp16.h>
#include <math.h>
#include <stdint.h>

#define T_TOK 4096      // B*S tokens
#define DIM   1024
#define NE    8
#define FF    4096
#define NPAIR (2*T_TOK)        // 8192 (token, expert) pairs
#define CAPP  9216             // 8192 + 8*128 padding (segments 128-aligned)

// ---------------- scratch (device globals; no allocation allowed) ----------
__device__ __half g_Hh[(size_t)CAPP * FF]; // SiLU(x@W1+b1), fp16
__device__ int   g_pair_tok[CAPP];         // token index per pair row (-1 = pad)
__device__ float g_pair_sc[CAPP];          // routing score per pair row
__device__ int   g_tok_e[NPAIR];
__device__ float g_tok_p[NPAIR];
__device__ int   g_counts[NE];
__device__ int   g_cursor[NE];
__device__ int   g_seg[NE + 1];            // 128-aligned segment starts

// ---------------- helpers ----------------------------------------------------
__device__ __forceinline__ uint32_t smem_u32(const void* p) {
    return (uint32_t)__cvta_generic_to_shared(p);
}
__device__ __forceinline__ uint32_t pack_h2(float a, float b) {
    __half2 h = __floats2half2_rn(a, b);
    return *(uint32_t*)&h;
}
__device__ __forceinline__ void mma_f16(float& c0, float& c1, float& c2, float& c3,
                                        uint32_t a0, uint32_t a1, uint32_t a2, uint32_t a3,
                                        uint32_t b0, uint32_t b1) {
    asm volatile(
        "mma.sync.aligned.m16n8k16.row.col.f32.f16.f16.f32 "
        "{%0,%1,%2,%3}, {%4,%5,%6,%7}, {%8,%9}, {%0,%1,%2,%3};"
        : "+f"(c0), "+f"(c1), "+f"(c2), "+f"(c3)
        : "r"(a0), "r"(a1), "r"(a2), "r"(a3), "r"(b0), "r"(b1));
}
__device__ __forceinline__ void ldsm_x4(uint32_t& r0, uint32_t& r1, uint32_t& r2,
                                        uint32_t& r3, uint32_t addr) {
    asm volatile("ldmatrix.sync.aligned.m8n8.x4.shared.b16 {%0,%1,%2,%3}, [%4];"
                 : "=r"(r0), "=r"(r1), "=r"(r2), "=r"(r3) : "r"(addr));
}
__device__ __forceinline__ void ldsm_x4t(uint32_t& r0, uint32_t& r1, uint32_t& r2,
                                         uint32_t& r3, uint32_t addr) {
    asm volatile("ldmatrix.sync.aligned.m8n8.x4.trans.shared.b16 {%0,%1,%2,%3}, [%4];"
                 : "=r"(r0), "=r"(r1), "=r"(r2), "=r"(r3) : "r"(addr));
}

// ---------------- small utility kernels ------------------------------------
__global__ void k_zero_out(float4* out) {
    int i = blockIdx.x * blockDim.x + threadIdx.x;
    out[i] = make_float4(0.f, 0.f, 0.f, 0.f);
}
__global__ void k_reset() {
    int i = threadIdx.x;
    if (i < NE) { g_counts[i] = 0; g_cursor[i] = 0; }
}

// ---------------- router: logits -> top2 -> softmax(top2) ------------------
__global__ void __launch_bounds__(128) k_router(
    const float* __restrict__ x, const float* __restrict__ noise,
    const float* __restrict__ gw, const float* __restrict__ gb,
    const float* __restrict__ nw, const float* __restrict__ nb)
{
    int t = blockIdx.x;
    int tid = threadIdx.x;
    __shared__ float sx[DIM];
    __shared__ float red[128];
    __shared__ float lg[NE];

    for (int i = tid; i < DIM; i += 128) sx[i] = x[(size_t)t * DIM + i];
    __syncthreads();

    int e = tid & 7;
    float s = 0.f;
    for (int d = (tid >> 3); d < DIM; d += 16)
        s += sx[d] * (gw[d * NE + e] + nw[d * NE + e]);
    red[tid] = s;
    __syncthreads();
    for (int off = 64; off >= 8; off >>= 1) {
        if (tid < off) red[tid] += red[tid + off];
        __syncthreads();
    }
    if (tid < NE)
        lg[tid] = red[tid] + gb[tid] + nb[tid] + noise[t * NE + tid];
    __syncthreads();

    if (tid == 0) {
        float v0 = -1e30f; int i0 = 0;
        #pragma unroll
        for (int k = 0; k < NE; k++) { float v = lg[k]; if (v > v0) { v0 = v; i0 = k; } }
        float v1 = -1e30f; int i1 = 0;
        #pragma unroll
        for (int k = 0; k < NE; k++) { if (k == i0) continue; float v = lg[k]; if (v > v1) { v1 = v; i1 = k; } }
        float e1 = expf(v1 - v0);
        float z = 1.f + e1;
        g_tok_e[2 * t] = i0;  g_tok_e[2 * t + 1] = i1;
        g_tok_p[2 * t] = 1.f / z;  g_tok_p[2 * t + 1] = e1 / z;
        atomicAdd(&g_counts[i0], 1);
        atomicAdd(&g_counts[i1], 1);
    }
}

__global__ void k_offsets() {
    if (threadIdx.x == 0) {
        int acc = 0;
        g_seg[0] = 0;
        for (int e = 0; e < NE; e++) {
            acc += ((g_counts[e] + 127) / 128) * 128;
            g_seg[e + 1] = acc;
        }
    }
}

__global__ void k_init_pairs() {
    int i = blockIdx.x * blockDim.x + threadIdx.x;
    if (i < CAPP) { g_pair_tok[i] = -1; g_pair_sc[i] = 0.f; }
}

__global__ void k_scatter() {
    int i = blockIdx.x * blockDim.x + threadIdx.x;
    if (i >= NPAIR) return;
    int t = i >> 1;
    int e = g_tok_e[i];
    float p = g_tok_p[i];
    int pos = g_seg[e] + atomicAdd(&g_cursor[e], 1);
    g_pair_tok[pos] = t;
    g_pair_sc[pos]  = p;
}

__device__ __forceinline__ int tile_expert(int row0) {
    int e = -1;
    #pragma unroll
    for (int i = 0; i < NE; i++)
        if (row0 >= g_seg[i] && row0 < g_seg[i + 1]) e = i;
    return e;
}

// ---------------- SMEM strides (halfs) --------------------------------------
#define AST 40    // As[128][40] halfs (80B row)  -> LDSM rows on distinct banks
#define BST 136   // Bs[32][136] halfs (272B row) -> LDSM rows on distinct banks

// =============================================================================
// fp16 mma.sync GEMM: 128x128 CTA tile, 8 warps (64x32 each), K-tile 32,
// A via ldmatrix.x4, B row-major [k][n] via ldmatrix.x4.trans
// =============================================================================

// GEMM1: g_Hh = fp16(SiLU(X_gather @ W1[e] + b1[e]));  W1 row-major [K][N]
__global__ void __launch_bounds__(256, 2) k_mma_gemm1(
    const float* __restrict__ x, const float* __restrict__ w1,
    const float* __restrict__ b1)
{
    __shared__ __half As[128 * AST];
    __shared__ __half Bs[32 * BST];
    __shared__ int stok[128];

    const int tid = threadIdx.x;
    const int n0 = blockIdx.x * 128;
    const int row0 = blockIdx.y * 128;
    const int e = tile_expert(row0);
    if (e < 0) return;
    const float* __restrict__ w = w1 + (size_t)e * DIM * FF;

    if (tid < 128) stok[tid] = g_pair_tok[row0 + tid];
    __syncthreads();

    const int lane = tid & 31;
    const int wrp = tid >> 5;
    const int wm = (wrp & 1) * 64;
    const int wn = (wrp >> 1) * 32;
    const int qr = lane >> 2;   // 0..7
    const uint32_t as_base = smem_u32(As);
    const uint32_t bs_base = smem_u32(Bs);

    float acc[4][4][4];
    #pragma unroll
    for (int i = 0; i < 4; i++)
        #pragma unroll
        for (int j = 0; j < 4; j++)
            #pragma unroll
            for (int q = 0; q < 4; q++) acc[i][j][q] = 0.f;

    // staging coords
    const int arow = tid >> 1;            // 0..127
    const int akh  = (tid & 1) * 16;      // half-index 0 or 16
    const int t_a = stok[arow];
    const float* __restrict__ xrow = (t_a >= 0) ? x + (size_t)t_a * DIM : x;
    const int bk = tid >> 3;              // 0..31
    const int bn = (tid & 7) * 16;        // 0..112

    // LDSM lane addresses (precomputed offsets)
    const int a_r = (lane & 15);
    const int a_k = (lane & 16) >> 1;     // 0 or 8
    const int b_k = (lane & 7) + ((lane & 8) ? 8 : 0);
    const int b_n = (lane & 16) >> 1;     // 0 or 8

    for (int kt = 0; kt < DIM; kt += 32) {
        // ---- stage A (gather fp32 -> fp16) ----
        {
            uint4 u0, u1;
            if (t_a >= 0) {
                float4 v0 = *(const float4*)(xrow + kt + akh);
                float4 v1 = *(const float4*)(xrow + kt + akh + 4);
                float4 v2 = *(const float4*)(xrow + kt + akh + 8);
                float4 v3 = *(const float4*)(xrow + kt + akh + 12);
                u0 = make_uint4(pack_h2(v0.x, v0.y), pack_h2(v0.z, v0.w),
                                pack_h2(v1.x, v1.y), pack_h2(v1.z, v1.w));
                u1 = make_uint4(pack_h2(v2.x, v2.y), pack_h2(v2.z, v2.w),
                                pack_h2(v3.x, v3.y), pack_h2(v3.z, v3.w));
            } else {
                u0 = make_uint4(0, 0, 0, 0); u1 = u0;
            }
            *(uint4*)&As[arow * AST + akh]     = u0;
            *(uint4*)&As[arow * AST + akh + 8] = u1;
        }
        // ---- stage B (fp32 -> fp16, keep [k][n] row-major) ----
        {
            const float* wr = w + (size_t)(kt + bk) * FF + n0 + bn;
            float4 v0 = *(const float4*)(wr);
            float4 v1 = *(const float4*)(wr + 4);
            float4 v2 = *(const float4*)(wr + 8);
            float4 v3 = *(const float4*)(wr + 12);
            *(uint4*)&Bs[bk * BST + bn] =
                make_uint4(pack_h2(v0.x, v0.y), pack_h2(v0.z, v0.w),
                           pack_h2(v1.x, v1.y), pack_h2(v1.z, v1.w));
            *(uint4*)&Bs[bk * BST + bn + 8] =
                make_uint4(pack_h2(v2.x, v2.y), pack_h2(v2.z, v2.w),
                           pack_h2(v3.x, v3.y), pack_h2(v3.z, v3.w));
        }
        __syncthreads();

        // ---- 2 x k=16 mma steps ----
        #pragma unroll
        for (int ks = 0; ks < 2; ++ks) {
            const int k0 = ks * 16;
            uint32_t af[4][4];
            #pragma unroll
            for (int i = 0; i < 4; ++i) {
                uint32_t ad = as_base + ((wm + i * 16 + a_r) * AST + k0 + a_k) * 2;
                ldsm_x4(af[i][0], af[i][1], af[i][2], af[i][3], ad);
            }
            uint32_t bf[4][2];
            #pragma unroll
            for (int jp = 0; jp < 2; ++jp) {
                uint32_t bd = bs_base + ((k0 + b_k) * BST + wn + jp * 16 + b_n) * 2;
                ldsm_x4t(bf[jp * 2][0], bf[jp * 2][1],
                         bf[jp * 2 + 1][0], bf[jp * 2 + 1][1], bd);
            }
            #pragma unroll
            for (int i = 0; i < 4; ++i)
                #pragma unroll
                for (int j = 0; j < 4; ++j)
                    mma_f16(acc[i][j][0], acc[i][j][1], acc[i][j][2], acc[i][j][3],
                            af[i][0], af[i][1], af[i][2], af[i][3],
                            bf[j][0], bf[j][1]);
        }
        __syncthreads();
    }

    // ---- epilogue: bias + SiLU -> g_Hh (fp16) ----
    const float* bp = b1 + (size_t)e * FF + n0;
    #pragma unroll
    for (int j = 0; j < 4; ++j) {
        int col = wn + j * 8 + (lane & 3) * 2;
        float bb0 = bp[col], bb1 = bp[col + 1];
        #pragma unroll
        for (int i = 0; i < 4; ++i) {
            int r0 = row0 + wm + i * 16 + qr;
            float a0 = acc[i][j][0] + bb0, a1 = acc[i][j][1] + bb1;
            uint32_t p0 = pack_h2(a0 / (1.f + __expf(-a0)), a1 / (1.f + __expf(-a1)));
            *(uint32_t*)&g_Hh[(size_t)r0 * FF + n0 + col] = p0;
            float a2 = acc[i][j][2] + bb0, a3 = acc[i][j][3] + bb1;
            uint32_t p1 = pack_h2(a2 / (1.f + __expf(-a2)), a3 / (1.f + __expf(-a3)));
            *(uint32_t*)&g_Hh[(size_t)(r0 + 8) * FF + n0 + col] = p1;
        }
    }
}

// GEMM2: out[t] += score * (g_Hh @ W2[e] + b2[e]);  W2 row-major [K][N]
__global__ void __launch_bounds__(256, 2) k_mma_gemm2(
    const float* __restrict__ w2, const float* __restrict__ b2,
    float* __restrict__ out)
{
    __shared__ __half As[128 * AST];
    __shared__ __half Bs[32 * BST];
    __shared__ int   stok[128];
    __shared__ float ssc[128];

    const int tid = threadIdx.x;
    const int n0 = blockIdx.x * 128;
    const int row0 = blockIdx.y * 128;
    const int e = tile_expert(row0);
    if (e < 0) return;
    const float* __restrict__ w = w2 + (size_t)e * FF * DIM;

    if (tid < 128) { stok[tid] = g_pair_tok[row0 + tid]; ssc[tid] = g_pair_sc[row0 + tid]; }
    __syncthreads();

    const int lane = tid & 31;
    const int wrp = tid >> 5;
    const int wm = (wrp & 1) * 64;
    const int wn = (wrp >> 1) * 32;
    const int qr = lane >> 2;
    const uint32_t as_base = smem_u32(As);
    const uint32_t bs_base = smem_u32(Bs);

    float acc[4][4][4];
    #pragma unroll
    for (int i = 0; i < 4; i++)
        #pragma unroll
        for (int j = 0; j < 4; j++)
            #pragma unroll
            for (int q = 0; q < 4; q++) acc[i][j][q] = 0.f;

    const int arow = tid >> 1;
    const int akh  = (tid & 1) * 16;
    const __half* __restrict__ hrow = g_Hh + (size_t)(row0 + arow) * FF + akh;
    const int bk = tid >> 3;
    const int bn = (tid & 7) * 16;

    const int a_r = (lane & 15);
    const int a_k = (lane & 16) >> 1;
    const int b_k = (lane & 7) + ((lane & 8) ? 8 : 0);
    const int b_n = (lane & 16) >> 1;

    for (int kt = 0; kt < FF; kt += 32) {
        // ---- stage A (fp16 direct copy) ----
        {
            uint4 u0 = *(const uint4*)(hrow + kt);
            uint4 u1 = *(const uint4*)(hrow + kt + 8);
            *(uint4*)&As[arow * AST + akh]     = u0;
            *(uint4*)&As[arow * AST + akh + 8] = u1;
        }
        // ---- stage B ----
        {
            const float* wr = w + (size_t)(kt + bk) * DIM + n0 + bn;
            float4 v0 = *(const float4*)(wr);
            float4 v1 = *(const float4*)(wr + 4);
            float4 v2 = *(const float4*)(wr + 8);
            float4 v3 = *(const float4*)(wr + 12);
            *(uint4*)&Bs[bk * BST + bn] =
                make_uint4(pack_h2(v0.x, v0.y), pack_h2(v0.z, v0.w),
                           pack_h2(v1.x, v1.y), pack_h2(v1.z, v1.w));
            *(uint4*)&Bs[bk * BST + bn + 8] =
                make_uint4(pack_h2(v2.x, v2.y), pack_h2(v2.z, v2.w),
                           pack_h2(v3.x, v3.y), pack_h2(v3.z, v3.w));
        }
        __syncthreads();

        #pragma unroll
        for (int ks = 0; ks < 2; ++ks) {
            const int k0 = ks * 16;
            uint32_t af[4][4];
            #pragma unroll
            for (int i = 0; i < 4; ++i) {
                uint32_t ad = as_base + ((wm + i * 16 + a_r) * AST + k0 + a_k) * 2;
                ldsm_x4(af[i][0], af[i][1], af[i][2], af[i][3], ad);
            }
            uint32_t bf[4][2];
            #pragma unroll
            for (int jp = 0; jp < 2; ++jp) {
                uint32_t bd = bs_base + ((k0 + b_k) * BST + wn + jp * 16 + b_n) * 2;
                ldsm_x4t(bf[jp * 2][0], bf[jp * 2][1],
                         bf[jp * 2 + 1][0], bf[jp * 2 + 1][1], bd);
            }
            #pragma unroll
            for (int i = 0; i < 4; ++i)
                #pragma unroll
                for (int j = 0; j < 4; ++j)
                    mma_f16(acc[i][j][0], acc[i][j][1], acc[i][j][2], acc[i][j][3],
                            af[i][0], af[i][1], af[i][2], af[i][3],
                            bf[j][0], bf[j][1]);
        }
        __syncthreads();
    }

    // ---- epilogue: bias + score * atomicAdd ----
    const float* bp = b2 + (size_t)e * DIM + n0;
    #pragma unroll
    for (int j = 0; j < 4; ++j) {
        int col = wn + j * 8 + (lane & 3) * 2;
        float bb0 = bp[col], bb1 = bp[col + 1];
        #pragma unroll
        for (int i = 0; i < 4; ++i) {
            int m = wm + i * 16 + qr;
            int t0 = stok[m], t1 = stok[m + 8];
            if (t0 >= 0) {
                float s = ssc[m];
                atomicAdd(&out[(size_t)t0 * DIM + n0 + col],     s * (acc[i][j][0] + bb0));
                atomicAdd(&out[(size_t)t0 * DIM + n0 + col + 1], s * (acc[i][j][1] + bb1));
            }
            if (t1 >= 0) {
                float s = ssc[m + 8];
                atomicAdd(&out[(size_t)t1 * DIM + n0 + col],     s * (acc[i][j][2] + bb0));
                atomicAdd(&out[(size_t)t1 * DIM + n0 + col + 1], s * (acc[i][j][3] + bb1));
            }
        }
    }
}

// ---------------- aux loss ---------------------------------------------------
__global__ void __launch_bounds__(256) k_aux(float* __restrict__ aux_out) {
    __shared__ float sred[256];
    __shared__ float simp[NE];
    int tid = threadIdx.x;
    float imp[NE];
    #pragma unroll
    for (int e = 0; e < NE; e++) imp[e] = 0.f;
    for (int t = tid; t < T_TOK; t += 256) {
        imp[g_tok_e[2 * t]]     += g_tok_p[2 * t];
        imp[g_tok_e[2 * t + 1]] += g_tok_p[2 * t + 1];
    }
    for (int e = 0; e < NE; e++) {
        sred[tid] = imp[e];
        __syncthreads();
        for (int off = 128; off > 0; off >>= 1) {
            if (tid < off) sred[tid] += sred[tid + off];
            __syncthreads();
        }
        if (tid == 0) simp[e] = sred[0] / (float)T_TOK;
        __syncthreads();
    }
    if (tid == 0) {
        float aux = 0.f;
        const float u = 1.f / (float)NE;
        const float logu = logf(u);
        #pragma unroll
        for (int e = 0; e < NE; e++)
            aux += u * (logu - logf(simp[e] + 1e-8f));
        aux_out[0] = aux;
    }
}

// ---------------- launch -----------------------------------------------------
extern "C" void kernel_launch(void* const* d_in, const int* in_sizes, int n_in,
                              void* d_out, int out_size) {
    const float* x       = (const float*)d_in[0];
    const float* noise   = (const float*)d_in[1];
    const float* gate_w  = (const float*)d_in[2];
    const float* gate_b  = (const float*)d_in[3];
    const float* noise_w = (const float*)d_in[4];
    const float* noise_b = (const float*)d_in[5];
    const float* w1      = (const float*)d_in[6];
    const float* b1      = (const float*)d_in[7];
    const float* w2      = (const float*)d_in[8];
    const float* b2      = (const float*)d_in[9];
    float* out = (float*)d_out;
    (void)in_sizes; (void)n_in;

    k_zero_out<<<(T_TOK * DIM / 4 + 255) / 256, 256>>>((float4*)out);
    k_reset<<<1, 32>>>();
    k_router<<<T_TOK, 128>>>(x, noise, gate_w, gate_b, noise_w, noise_b);
    k_offsets<<<1, 32>>>();
    k_init_pairs<<<(CAPP + 255) / 256, 256>>>();
    k_scatter<<<(NPAIR + 255) / 256, 256>>>();
    k_mma_gemm1<<<dim3(FF / 128, CAPP / 128), 256>>>(x, w1, b1);
    k_mma_gemm2<<<dim3(DIM / 128, CAPP / 128), 256>>>(w2, b2, out);
    k_aux<<<1, 256>>>(out + (out_size - 1));
}

// round 5
// speedup vs baseline: 6.3358x; 1.5499x over previous
#include <cuda_runtime.h>
#include <cuda_fp16.h>
#include <math.h>
#include <stdint.h>

#define T_TOK 4096      // B*S tokens
#define DIM   1024
#define NE    8
#define FF    4096
#define NPAIR (2*T_TOK)        // 8192 (token, expert) pairs
#define CAPP  9216             // 8192 + 8*128 padding (segments 128-aligned)

// ---------------- scratch (device globals; no allocation allowed) ----------
__device__ __half g_Hh[(size_t)CAPP * FF];       // SiLU(x@W1+b1), fp16
__device__ __half g_xh[(size_t)T_TOK * DIM];     // x in fp16
__device__ __half g_w1h[(size_t)NE * DIM * FF];  // W1 in fp16
__device__ __half g_w2h[(size_t)NE * FF * DIM];  // W2 in fp16
__device__ int   g_pair_tok[CAPP];
__device__ float g_pair_sc[CAPP];
__device__ int   g_tok_e[NPAIR];
__device__ float g_tok_p[NPAIR];
__device__ int   g_counts[NE];
__device__ int   g_cursor[NE];
__device__ int   g_seg[NE + 1];

// ---------------- helpers ----------------------------------------------------
__device__ __forceinline__ uint32_t smem_u32(const void* p) {
    return (uint32_t)__cvta_generic_to_shared(p);
}
__device__ __forceinline__ uint32_t pack_h2(float a, float b) {
    __half2 h = __floats2half2_rn(a, b);
    return *(uint32_t*)&h;
}
__device__ __forceinline__ void mma_f16(float& c0, float& c1, float& c2, float& c3,
                                        uint32_t a0, uint32_t a1, uint32_t a2, uint32_t a3,
                                        uint32_t b0, uint32_t b1) {
    asm volatile(
        "mma.sync.aligned.m16n8k16.row.col.f32.f16.f16.f32 "
        "{%0,%1,%2,%3}, {%4,%5,%6,%7}, {%8,%9}, {%0,%1,%2,%3};"
        : "+f"(c0), "+f"(c1), "+f"(c2), "+f"(c3)
        : "r"(a0), "r"(a1), "r"(a2), "r"(a3), "r"(b0), "r"(b1));
}
__device__ __forceinline__ void ldsm_x4(uint32_t& r0, uint32_t& r1, uint32_t& r2,
                                        uint32_t& r3, uint32_t addr) {
    asm volatile("ldmatrix.sync.aligned.m8n8.x4.shared.b16 {%0,%1,%2,%3}, [%4];"
                 : "=r"(r0), "=r"(r1), "=r"(r2), "=r"(r3) : "r"(addr));
}
__device__ __forceinline__ void ldsm_x4t(uint32_t& r0, uint32_t& r1, uint32_t& r2,
                                         uint32_t& r3, uint32_t addr) {
    asm volatile("ldmatrix.sync.aligned.m8n8.x4.trans.shared.b16 {%0,%1,%2,%3}, [%4];"
                 : "=r"(r0), "=r"(r1), "=r"(r2), "=r"(r3) : "r"(addr));
}
__device__ __forceinline__ void cpa16(uint32_t dst, const void* src) {
    asm volatile("cp.async.cg.shared.global [%0], [%1], 16;"
                 :: "r"(dst), "l"(src));
}
#define CP_COMMIT() asm volatile("cp.async.commit_group;" ::: "memory")
#define CP_WAIT2()  asm volatile("cp.async.wait_group 2;"  ::: "memory")

// ---------------- small utility kernels ------------------------------------
__global__ void k_zero_out(float4* out) {
    int i = blockIdx.x * blockDim.x + threadIdx.x;
    out[i] = make_float4(0.f, 0.f, 0.f, 0.f);
}
__global__ void k_reset() {
    int i = threadIdx.x;
    if (i < NE) { g_counts[i] = 0; g_cursor[i] = 0; }
}
// fp32 -> fp16 bulk convert (8 elems / thread)
__global__ void k_cvt(const float4* __restrict__ src, uint4* __restrict__ dst, int n8) {
    int i = blockIdx.x * blockDim.x + threadIdx.x;
    if (i >= n8) return;
    float4 v0 = src[2 * i], v1 = src[2 * i + 1];
    dst[i] = make_uint4(pack_h2(v0.x, v0.y), pack_h2(v0.z, v0.w),
                        pack_h2(v1.x, v1.y), pack_h2(v1.z, v1.w));
}

// ---------------- router: logits -> top2 -> softmax(top2) ------------------
__global__ void __launch_bounds__(128) k_router(
    const float* __restrict__ x, const float* __restrict__ noise,
    const float* __restrict__ gw, const float* __restrict__ gb,
    const float* __restrict__ nw, const float* __restrict__ nb)
{
    int t = blockIdx.x;
    int tid = threadIdx.x;
    __shared__ float sx[DIM];
    __shared__ float red[128];
    __shared__ float lg[NE];

    for (int i = tid; i < DIM; i += 128) sx[i] = x[(size_t)t * DIM + i];
    __syncthreads();

    int e = tid & 7;
    float s = 0.f;
    for (int d = (tid >> 3); d < DIM; d += 16)
        s += sx[d] * (gw[d * NE + e] + nw[d * NE + e]);
    red[tid] = s;
    __syncthreads();
    for (int off = 64; off >= 8; off >>= 1) {
        if (tid < off) red[tid] += red[tid + off];
        __syncthreads();
    }
    if (tid < NE)
        lg[tid] = red[tid] + gb[tid] + nb[tid] + noise[t * NE + tid];
    __syncthreads();

    if (tid == 0) {
        float v0 = -1e30f; int i0 = 0;
        #pragma unroll
        for (int k = 0; k < NE; k++) { float v = lg[k]; if (v > v0) { v0 = v; i0 = k; } }
        float v1 = -1e30f; int i1 = 0;
        #pragma unroll
        for (int k = 0; k < NE; k++) { if (k == i0) continue; float v = lg[k]; if (v > v1) { v1 = v; i1 = k; } }
        float e1 = expf(v1 - v0);
        float z = 1.f + e1;
        g_tok_e[2 * t] = i0;  g_tok_e[2 * t + 1] = i1;
        g_tok_p[2 * t] = 1.f / z;  g_tok_p[2 * t + 1] = e1 / z;
        atomicAdd(&g_counts[i0], 1);
        atomicAdd(&g_counts[i1], 1);
    }
}

__global__ void k_offsets() {
    if (threadIdx.x == 0) {
        int acc = 0;
        g_seg[0] = 0;
        for (int e = 0; e < NE; e++) {
            acc += ((g_counts[e] + 127) / 128) * 128;
            g_seg[e + 1] = acc;
        }
    }
}
__global__ void k_init_pairs() {
    int i = blockIdx.x * blockDim.x + threadIdx.x;
    if (i < CAPP) { g_pair_tok[i] = -1; g_pair_sc[i] = 0.f; }
}
__global__ void k_scatter() {
    int i = blockIdx.x * blockDim.x + threadIdx.x;
    if (i >= NPAIR) return;
    int t = i >> 1;
    int e = g_tok_e[i];
    float p = g_tok_p[i];
    int pos = g_seg[e] + atomicAdd(&g_cursor[e], 1);
    g_pair_tok[pos] = t;
    g_pair_sc[pos]  = p;
}
__device__ __forceinline__ int tile_expert(int row0) {
    int e = -1;
    #pragma unroll
    for (int i = 0; i < NE; i++)
        if (row0 >= g_seg[i] && row0 < g_seg[i + 1]) e = i;
    return e;
}

// ---------------- SMEM geometry (halfs) --------------------------------------
#define AST 40               // A row stride (80B, 16B-aligned, LDSM conflict-free)
#define BST 136              // B row stride (272B, 16B-aligned, conflict-free)
#define A_STAGE_H (128 * AST)    // 5120 halfs
#define B_STAGE_H (32 * BST)     // 4352 halfs
#define NSTAGE 3
#define GEMM_SMEM ((A_STAGE_H + B_STAGE_H) * NSTAGE * 2)   // 56832 B

// =============================================================================
// fp16 mma.sync GEMM, 128x128 CTA tile, 8 warps, K-tile 32, 3-stage cp.async
// =============================================================================

// GEMM1: g_Hh = fp16(SiLU(Xh_gather @ W1h[e] + b1[e]))
__global__ void __launch_bounds__(256, 2) k_mma_gemm1(const float* __restrict__ b1)
{
    extern __shared__ __half sm[];
    __half* As = sm;                            // [NSTAGE][128][AST]
    __half* Bs = sm + NSTAGE * A_STAGE_H;       // [NSTAGE][32][BST]
    __shared__ int stok[128];

    const int tid = threadIdx.x;
    const int n0 = blockIdx.x * 128;
    const int row0 = blockIdx.y * 128;
    const int e = tile_expert(row0);
    if (e < 0) return;
    const __half* __restrict__ w = g_w1h + (size_t)e * DIM * FF;

    if (tid < 128) stok[tid] = g_pair_tok[row0 + tid];
    __syncthreads();

    const int lane = tid & 31;
    const int wrp = tid >> 5;
    const int wm = (wrp & 1) * 64;
    const int wn = (wrp >> 1) * 32;
    const int qr = lane >> 2;
    const uint32_t as_base = smem_u32(As);
    const uint32_t bs_base = smem_u32(Bs);

    // staging coords: A = 2 chunks (rows r0, r0+64), B = 2 chunks (rows br, br+16)
    const int ar = tid >> 2;                 // 0..63
    const int ac8 = (tid & 3) * 8;           // half offset 0/8/16/24
    int ta0 = stok[ar];     if (ta0 < 0) ta0 = 0;
    int ta1 = stok[ar + 64]; if (ta1 < 0) ta1 = 0;
    const __half* xr0 = g_xh + (size_t)ta0 * DIM + ac8;
    const __half* xr1 = g_xh + (size_t)ta1 * DIM + ac8;
    const int br = tid >> 4;                 // 0..15
    const int bc8 = (tid & 15) * 8;
    const __half* wr = w + n0 + bc8;

    const uint32_t a_d0 = as_base + (ar * AST + ac8) * 2;
    const uint32_t a_d1 = as_base + ((ar + 64) * AST + ac8) * 2;
    const uint32_t b_d0 = bs_base + (br * BST + bc8) * 2;
    const uint32_t b_d1 = bs_base + ((br + 16) * BST + bc8) * 2;

    // LDSM lane offsets
    const int a_r = (lane & 15);
    const int a_k = (lane & 16) >> 1;
    const int b_k = (lane & 7) + ((lane & 8) ? 8 : 0);
    const int b_n = (lane & 16) >> 1;

    float acc[4][4][4];
    #pragma unroll
    for (int i = 0; i < 4; i++)
        #pragma unroll
        for (int j = 0; j < 4; j++)
            #pragma unroll
            for (int q = 0; q < 4; q++) acc[i][j][q] = 0.f;

    const int NK = DIM / 32;
    // prologue: stages 0,1
    #pragma unroll
    for (int s = 0; s < NSTAGE - 1; ++s) {
        int kt = s * 32;
        uint32_t ao = s * A_STAGE_H * 2, bo = s * B_STAGE_H * 2;
        cpa16(a_d0 + ao, xr0 + kt);
        cpa16(a_d1 + ao, xr1 + kt);
        cpa16(b_d0 + bo, wr + (size_t)(kt + br) * FF);
        cpa16(b_d1 + bo, wr + (size_t)(kt + br + 16) * FF);
        CP_COMMIT();
    }

    for (int ki = 0; ki < NK; ++ki) {
        int kf = ki + NSTAGE - 1;
        if (kf < NK) {
            int s = kf % NSTAGE;
            int kt = kf * 32;
            uint32_t ao = s * A_STAGE_H * 2, bo = s * B_STAGE_H * 2;
            cpa16(a_d0 + ao, xr0 + kt);
            cpa16(a_d1 + ao, xr1 + kt);
            cpa16(b_d0 + bo, wr + (size_t)(kt + br) * FF);
            cpa16(b_d1 + bo, wr + (size_t)(kt + br + 16) * FF);
        }
        CP_COMMIT();
        CP_WAIT2();
        __syncthreads();

        const int s = ki % NSTAGE;
        const uint32_t asb = as_base + s * A_STAGE_H * 2;
        const uint32_t bsb = bs_base + s * B_STAGE_H * 2;
        #pragma unroll
        for (int ks = 0; ks < 2; ++ks) {
            const int k0 = ks * 16;
            uint32_t af[4][4];
            #pragma unroll
            for (int i = 0; i < 4; ++i) {
                uint32_t ad = asb + ((wm + i * 16 + a_r) * AST + k0 + a_k) * 2;
                ldsm_x4(af[i][0], af[i][1], af[i][2], af[i][3], ad);
            }
            uint32_t bf[4][2];
            #pragma unroll
            for (int jp = 0; jp < 2; ++jp) {
                uint32_t bd = bsb + ((k0 + b_k) * BST + wn + jp * 16 + b_n) * 2;
                ldsm_x4t(bf[jp * 2][0], bf[jp * 2][1],
                         bf[jp * 2 + 1][0], bf[jp * 2 + 1][1], bd);
            }
            #pragma unroll
            for (int i = 0; i < 4; ++i)
                #pragma unroll
                for (int j = 0; j < 4; ++j)
                    mma_f16(acc[i][j][0], acc[i][j][1], acc[i][j][2], acc[i][j][3],
                            af[i][0], af[i][1], af[i][2], af[i][3],
                            bf[j][0], bf[j][1]);
        }
        __syncthreads();
    }

    // epilogue: bias + SiLU -> g_Hh (fp16)
    const float* bp = b1 + (size_t)e * FF + n0;
    #pragma unroll
    for (int j = 0; j < 4; ++j) {
        int col = wn + j * 8 + (lane & 3) * 2;
        float bb0 = bp[col], bb1 = bp[col + 1];
        #pragma unroll
        for (int i = 0; i < 4; ++i) {
            int r0 = row0 + wm + i * 16 + qr;
            float a0 = acc[i][j][0] + bb0, a1 = acc[i][j][1] + bb1;
            uint32_t p0 = pack_h2(a0 / (1.f + __expf(-a0)), a1 / (1.f + __expf(-a1)));
            *(uint32_t*)&g_Hh[(size_t)r0 * FF + n0 + col] = p0;
            float a2 = acc[i][j][2] + bb0, a3 = acc[i][j][3] + bb1;
            uint32_t p1 = pack_h2(a2 / (1.f + __expf(-a2)), a3 / (1.f + __expf(-a3)));
            *(uint32_t*)&g_Hh[(size_t)(r0 + 8) * FF + n0 + col] = p1;
        }
    }
}

// GEMM2: out[t] += score * (g_Hh @ W2h[e] + b2[e])
__global__ void __launch_bounds__(256, 2) k_mma_gemm2(
    const float* __restrict__ b2, float* __restrict__ out)
{
    extern __shared__ __half sm[];
    __half* As = sm;
    __half* Bs = sm + NSTAGE * A_STAGE_H;
    __shared__ int   stok[128];
    __shared__ float ssc[128];

    const int tid = threadIdx.x;
    const int n0 = blockIdx.x * 128;
    const int row0 = blockIdx.y * 128;
    const int e = tile_expert(row0);
    if (e < 0) return;
    const __half* __restrict__ w = g_w2h + (size_t)e * FF * DIM;

    if (tid < 128) { stok[tid] = g_pair_tok[row0 + tid]; ssc[tid] = g_pair_sc[row0 + tid]; }
    __syncthreads();

    const int lane = tid & 31;
    const int wrp = tid >> 5;
    const int wm = (wrp & 1) * 64;
    const int wn = (wrp >> 1) * 32;
    const int qr = lane >> 2;
    const uint32_t as_base = smem_u32(As);
    const uint32_t bs_base = smem_u32(Bs);

    const int ar = tid >> 2;
    const int ac8 = (tid & 3) * 8;
    const __half* hr0 = g_Hh + (size_t)(row0 + ar) * FF + ac8;
    const __half* hr1 = g_Hh + (size_t)(row0 + ar + 64) * FF + ac8;
    const int br = tid >> 4;
    const int bc8 = (tid & 15) * 8;
    const __half* wr = w + n0 + bc8;

    const uint32_t a_d0 = as_base + (ar * AST + ac8) * 2;
    const uint32_t a_d1 = as_base + ((ar + 64) * AST + ac8) * 2;
    const uint32_t b_d0 = bs_base + (br * BST + bc8) * 2;
    const uint32_t b_d1 = bs_base + ((br + 16) * BST + bc8) * 2;

    const int a_r = (lane & 15);
    const int a_k = (lane & 16) >> 1;
    const int b_k = (lane & 7) + ((lane & 8) ? 8 : 0);
    const int b_n = (lane & 16) >> 1;

    float acc[4][4][4];
    #pragma unroll
    for (int i = 0; i < 4; i++)
        #pragma unroll
        for (int j = 0; j < 4; j++)
            #pragma unroll
            for (int q = 0; q < 4; q++) acc[i][j][q] = 0.f;

    const int NK = FF / 32;
    #pragma unroll
    for (int s = 0; s < NSTAGE - 1; ++s) {
        int kt = s * 32;
        uint32_t ao = s * A_STAGE_H * 2, bo = s * B_STAGE_H * 2;
        cpa16(a_d0 + ao, hr0 + kt);
        cpa16(a_d1 + ao, hr1 + kt);
        cpa16(b_d0 + bo, wr + (size_t)(kt + br) * DIM);
        cpa16(b_d1 + bo, wr + (size_t)(kt + br + 16) * DIM);
        CP_COMMIT();
    }

    for (int ki = 0; ki < NK; ++ki) {
        int kf = ki + NSTAGE - 1;
        if (kf < NK) {
            int s = kf % NSTAGE;
            int kt = kf * 32;
            uint32_t ao = s * A_STAGE_H * 2, bo = s * B_STAGE_H * 2;
            cpa16(a_d0 + ao, hr0 + kt);
            cpa16(a_d1 + ao, hr1 + kt);
            cpa16(b_d0 + bo, wr + (size_t)(kt + br) * DIM);
            cpa16(b_d1 + bo, wr + (size_t)(kt + br + 16) * DIM);
        }
        CP_COMMIT();
        CP_WAIT2();
        __syncthreads();

        const int s = ki % NSTAGE;
        const uint32_t asb = as_base + s * A_STAGE_H * 2;
        const uint32_t bsb = bs_base + s * B_STAGE_H * 2;
        #pragma unroll
        for (int ks = 0; ks < 2; ++ks) {
            const int k0 = ks * 16;
            uint32_t af[4][4];
            #pragma unroll
            for (int i = 0; i < 4; ++i) {
                uint32_t ad = asb + ((wm + i * 16 + a_r) * AST + k0 + a_k) * 2;
                ldsm_x4(af[i][0], af[i][1], af[i][2], af[i][3], ad);
            }
            uint32_t bf[4][2];
            #pragma unroll
            for (int jp = 0; jp < 2; ++jp) {
                uint32_t bd = bsb + ((k0 + b_k) * BST + wn + jp * 16 + b_n) * 2;
                ldsm_x4t(bf[jp * 2][0], bf[jp * 2][1],
                         bf[jp * 2 + 1][0], bf[jp * 2 + 1][1], bd);
            }
            #pragma unroll
            for (int i = 0; i < 4; ++i)
                #pragma unroll
                for (int j = 0; j < 4; ++j)
                    mma_f16(acc[i][j][0], acc[i][j][1], acc[i][j][2], acc[i][j][3],
                            af[i][0], af[i][1], af[i][2], af[i][3],
                            bf[j][0], bf[j][1]);
        }
        __syncthreads();
    }

    // epilogue: bias + score * atomicAdd
    const float* bp = b2 + (size_t)e * DIM + n0;
    #pragma unroll
    for (int j = 0; j < 4; ++j) {
        int col = wn + j * 8 + (lane & 3) * 2;
        float bb0 = bp[col], bb1 = bp[col + 1];
        #pragma unroll
        for (int i = 0; i < 4; ++i) {
            int m = wm + i * 16 + qr;
            int t0 = stok[m], t1 = stok[m + 8];
            if (t0 >= 0) {
                float s = ssc[m];
                atomicAdd(&out[(size_t)t0 * DIM + n0 + col],     s * (acc[i][j][0] + bb0));
                atomicAdd(&out[(size_t)t0 * DIM + n0 + col + 1], s * (acc[i][j][1] + bb1));
            }
            if (t1 >= 0) {
                float s = ssc[m + 8];
                atomicAdd(&out[(size_t)t1 * DIM + n0 + col],     s * (acc[i][j][2] + bb0));
                atomicAdd(&out[(size_t)t1 * DIM + n0 + col + 1], s * (acc[i][j][3] + bb1));
            }
        }
    }
}

// ---------------- aux loss ---------------------------------------------------
__global__ void __launch_bounds__(256) k_aux(float* __restrict__ aux_out) {
    __shared__ float sred[256];
    __shared__ float simp[NE];
    int tid = threadIdx.x;
    float imp[NE];
    #pragma unroll
    for (int e = 0; e < NE; e++) imp[e] = 0.f;
    for (int t = tid; t < T_TOK; t += 256) {
        imp[g_tok_e[2 * t]]     += g_tok_p[2 * t];
        imp[g_tok_e[2 * t + 1]] += g_tok_p[2 * t + 1];
    }
    for (int e = 0; e < NE; e++) {
        sred[tid] = imp[e];
        __syncthreads();
        for (int off = 128; off > 0; off >>= 1) {
            if (tid < off) sred[tid] += sred[tid + off];
            __syncthreads();
        }
        if (tid == 0) simp[e] = sred[0] / (float)T_TOK;
        __syncthreads();
    }
    if (tid == 0) {
        float aux = 0.f;
        const float u = 1.f / (float)NE;
        const float logu = logf(u);
        #pragma unroll
        for (int e = 0; e < NE; e++)
            aux += u * (logu - logf(simp[e] + 1e-8f));
        aux_out[0] = aux;
    }
}

// ---------------- launch -----------------------------------------------------
extern "C" void kernel_launch(void* const* d_in, const int* in_sizes, int n_in,
                              void* d_out, int out_size) {
    const float* x       = (const float*)d_in[0];
    const float* noise   = (const float*)d_in[1];
    const float* gate_w  = (const float*)d_in[2];
    const float* gate_b  = (const float*)d_in[3];
    const float* noise_w = (const float*)d_in[4];
    const float* noise_b = (const float*)d_in[5];
    const float* w1      = (const float*)d_in[6];
    const float* b1      = (const float*)d_in[7];
    const float* w2      = (const float*)d_in[8];
    const float* b2      = (const float*)d_in[9];
    float* out = (float*)d_out;
    (void)in_sizes; (void)n_in;

    static bool attr_done = false;
    if (!attr_done) {
        cudaFuncSetAttribute(k_mma_gemm1, cudaFuncAttributeMaxDynamicSharedMemorySize, GEMM_SMEM);
        cudaFuncSetAttribute(k_mma_gemm2, cudaFuncAttributeMaxDynamicSharedMemorySize, GEMM_SMEM);
        attr_done = true;
    }

    // fp16 pre-conversion
    __half* d_xh; cudaGetSymbolAddress((void**)&d_xh, g_xh);
    __half* d_w1h; cudaGetSymbolAddress((void**)&d_w1h, g_w1h);
    __half* d_w2h; cudaGetSymbolAddress((void**)&d_w2h, g_w2h);
    {
        int n8 = T_TOK * DIM / 8;
        k_cvt<<<(n8 + 255) / 256, 256>>>((const float4*)x, (uint4*)d_xh, n8);
        n8 = NE * DIM * FF / 8;
        k_cvt<<<(n8 + 255) / 256, 256>>>((const float4*)w1, (uint4*)d_w1h, n8);
        k_cvt<<<(n8 + 255) / 256, 256>>>((const float4*)w2, (uint4*)d_w2h, n8);
    }

    k_zero_out<<<(T_TOK * DIM / 4 + 255) / 256, 256>>>((float4*)out);
    k_reset<<<1, 32>>>();
    k_router<<<T_TOK, 128>>>(x, noise, gate_w, gate_b, noise_w, noise_b);
    k_offsets<<<1, 32>>>();
    k_init_pairs<<<(CAPP + 255) / 256, 256>>>();
    k_scatter<<<(NPAIR + 255) / 256, 256>>>();
    k_mma_gemm1<<<dim3(FF / 128, CAPP / 128), 256, GEMM_SMEM>>>(b1);
    k_mma_gemm2<<<dim3(DIM / 128, CAPP / 128), 256, GEMM_SMEM>>>(b2, out);
    k_aux<<<1, 256>>>(out + (out_size - 1));
}